// round 1
// baseline (speedup 1.0000x reference)
#include <cuda_runtime.h>
#include <math.h>

// Problem dims
#define BB 128
#define PP 196
#define EE 2048
#define HH 512
#define VV 10000
#define TT 20
#define SS 19            // decode steps = T-1
#define XK 3072          // H + E + H  (concat input for fused gates GEMM)
#define G4 2048          // 4*H

// ---------------- scratch (device globals; no allocation allowed) ----------------
__device__ float g_Ws[(size_t)BB * PP * HH];    // 51.4 MB  precomputed img@W_att + bW
__device__ float g_Wcat[(size_t)XK * G4];       // 25.2 MB  [Wl ; Ul]
__device__ float g_X[BB * XK];                  // [emb | gate*ctx | h]
__device__ float g_avg[BB * EE];
__device__ float g_c[BB * HH];
__device__ float g_q[BB * HH];
__device__ float g_gate[BB * EE];
__device__ float g_gates[BB * G4];
__device__ float g_alpha[BB * PP];

// ---------------- fast-math helpers ----------------
__device__ __forceinline__ float ex2f(float x) { float r; asm("ex2.approx.f32 %0,%1;" : "=f"(r) : "f"(x)); return r; }
__device__ __forceinline__ float rcpf(float x) { float r; asm("rcp.approx.f32 %0,%1;" : "=f"(r) : "f"(x)); return r; }
// tanh via ex2+rcp: rel err ~1e-7 (used only in the hot attention loop)
__device__ __forceinline__ float tanh_fast(float x) {
    float ax = fabsf(x);
    float e  = ex2f(ax * -2.8853900817779268f);   // exp(-2|x|)
    float r  = (1.0f - e) * rcpf(1.0f + e);
    return copysignf(r, x);
}

// ---------------- generic fp32 GEMM, BM=64 BN=32 BK=16, 256 thr, 4x2 microtile ----
// C[M,N] = act(A[M,K] @ W[K,N] + bias[N]) ; M % 64 == 0 ; K % 16 == 0 ; N guarded
// ACT: 0 = none, 1 = tanh (accurate), 2 = sigmoid (accurate)
template <int ACT>
__global__ void __launch_bounds__(256)
gemm64(const float* __restrict__ A, const float* __restrict__ W,
       const float* __restrict__ bias, float* __restrict__ C,
       int N, int K, int lda, int ldc)
{
    __shared__ float As[16][68];   // transposed A tile, padded
    __shared__ float Bs[16][32];
    const int m0  = blockIdx.y * 64;
    const int n0  = blockIdx.x * 32;
    const int tid = threadIdx.x;
    const int tx  = tid & 15, ty = tid >> 4;

    float acc[4][2] = {};
    const int ar = tid >> 2;            // 0..63  (A row within tile)
    const int ak = (tid & 3) << 2;      // 0,4,8,12 (k offset, float4)
    const int wr = tid >> 4;            // 0..15 (W k-row)
    const int wc = (tid & 15) << 1;     // 0..30 (W col pair)

    const float* Ag = A + (size_t)(m0 + ar) * lda + ak;

    for (int k0 = 0; k0 < K; k0 += 16) {
        float4 av = *(const float4*)(Ag + k0);
        As[ak + 0][ar] = av.x; As[ak + 1][ar] = av.y;
        As[ak + 2][ar] = av.z; As[ak + 3][ar] = av.w;

        int wn = n0 + wc;
        float2 wv;
        wv.x = (wn     < N) ? W[(size_t)(k0 + wr) * N + wn    ] : 0.0f;
        wv.y = (wn + 1 < N) ? W[(size_t)(k0 + wr) * N + wn + 1] : 0.0f;
        Bs[wr][wc] = wv.x; Bs[wr][wc + 1] = wv.y;
        __syncthreads();

        #pragma unroll
        for (int kk = 0; kk < 16; kk++) {
            float4 a = *(const float4*)&As[kk][ty << 2];
            float  w0 = Bs[kk][tx << 1], w1 = Bs[kk][(tx << 1) + 1];
            acc[0][0] += a.x * w0; acc[0][1] += a.x * w1;
            acc[1][0] += a.y * w0; acc[1][1] += a.y * w1;
            acc[2][0] += a.z * w0; acc[2][1] += a.z * w1;
            acc[3][0] += a.w * w0; acc[3][1] += a.w * w1;
        }
        __syncthreads();
    }

    #pragma unroll
    for (int i = 0; i < 4; i++) {
        int m = m0 + (ty << 2) + i;
        #pragma unroll
        for (int j = 0; j < 2; j++) {
            int n = n0 + (tx << 1) + j;
            if (n < N) {
                float v = acc[i][j] + bias[n];
                if (ACT == 1)      v = tanhf(v);
                else if (ACT == 2) v = 1.0f / (1.0f + expf(-v));
                C[(size_t)m * ldc + n] = v;
            }
        }
    }
}

// ---------------- big GEMM for W_s precompute: BM=128 BN=64 BK=16, 8x4 microtile --
// Requirements: M%128==0, N%64==0, K%16==0 (W_s: 25088 x 512, K=2048)
__global__ void __launch_bounds__(256)
gemm128(const float* __restrict__ A, const float* __restrict__ W,
        const float* __restrict__ bias, float* __restrict__ C,
        int N, int K, int lda, int ldc)
{
    __shared__ float As[16][132];
    __shared__ float Bs[16][64];
    const int m0  = blockIdx.y * 128;
    const int n0  = blockIdx.x * 64;
    const int tid = threadIdx.x;
    const int tx  = tid & 15, ty = tid >> 4;

    float acc[8][4] = {};
    const int ar = tid >> 1;           // 0..127
    const int ak = (tid & 1) << 3;     // 0 or 8
    const int wr = tid >> 4;           // 0..15
    const int wc = (tid & 15) << 2;    // 0..60

    const float* Ag = A + (size_t)(m0 + ar) * lda + ak;

    for (int k0 = 0; k0 < K; k0 += 16) {
        float4 a0 = *(const float4*)(Ag + k0);
        float4 a1 = *(const float4*)(Ag + k0 + 4);
        As[ak + 0][ar] = a0.x; As[ak + 1][ar] = a0.y; As[ak + 2][ar] = a0.z; As[ak + 3][ar] = a0.w;
        As[ak + 4][ar] = a1.x; As[ak + 5][ar] = a1.y; As[ak + 6][ar] = a1.z; As[ak + 7][ar] = a1.w;

        float4 wv = *(const float4*)(W + (size_t)(k0 + wr) * N + n0 + wc);
        *(float4*)&Bs[wr][wc] = wv;
        __syncthreads();

        #pragma unroll
        for (int kk = 0; kk < 16; kk++) {
            float a[8], w[4];
            *(float4*)&a[0] = *(const float4*)&As[kk][ty << 3];
            *(float4*)&a[4] = *(const float4*)&As[kk][(ty << 3) + 4];
            *(float4*)&w[0] = *(const float4*)&Bs[kk][tx << 2];
            #pragma unroll
            for (int i = 0; i < 8; i++)
                #pragma unroll
                for (int j = 0; j < 4; j++)
                    acc[i][j] += a[i] * w[j];
        }
        __syncthreads();
    }

    #pragma unroll
    for (int i = 0; i < 8; i++) {
        int m = m0 + (ty << 3) + i;
        #pragma unroll
        for (int j = 0; j < 4; j++) {
            int n = n0 + (tx << 2) + j;
            C[(size_t)m * ldc + n] = acc[i][j] + bias[n];
        }
    }
}

// ---------------- small kernels ----------------
__global__ void copy_kernel(const float4* __restrict__ src, float4* __restrict__ dst, int n4)
{
    int i = blockIdx.x * 256 + threadIdx.x;
    if (i < n4) dst[i] = src[i];
}

__global__ void avg_kernel(const float* __restrict__ img, float* __restrict__ avg)
{
    int b = blockIdx.y;
    int e = blockIdx.x * 256 + threadIdx.x;
    const float* ib = img + (size_t)b * PP * EE + e;
    float s0 = 0, s1 = 0, s2 = 0, s3 = 0;
    #pragma unroll 4
    for (int p = 0; p < PP; p += 4) {
        s0 += ib[(size_t)(p    ) * EE];
        s1 += ib[(size_t)(p + 1) * EE];
        s2 += ib[(size_t)(p + 2) * EE];
        s3 += ib[(size_t)(p + 3) * EE];
    }
    avg[b * EE + e] = (s0 + s1 + s2 + s3) * (1.0f / PP);
}

// e[b,p] = sum_h v[h]*tanh(Ws[b,p,h]+q[b,h]) + bv ; alpha = softmax_p(e)
__global__ void __launch_bounds__(256)
attention_kernel(const float* __restrict__ Ws, const float* __restrict__ q,
                 const float* __restrict__ v_att, const float* __restrict__ bv,
                 float* __restrict__ alpha, float* __restrict__ alpha_out)
{
    __shared__ float qs[HH], vs[HH], es[PP], red[8];
    const int b = blockIdx.x;
    const int tid = threadIdx.x;
    const int lane = tid & 31, warp = tid >> 5;

    for (int i = tid; i < HH; i += 256) { qs[i] = q[b * HH + i]; vs[i] = v_att[i]; }
    __syncthreads();

    const float* Wb = Ws + (size_t)b * PP * HH;
    const float bv0 = bv[0];

    for (int p = warp; p < PP; p += 8) {
        const float* row = Wb + (size_t)p * HH;
        float s = 0.0f;
        #pragma unroll
        for (int i = 0; i < HH / 32; i++) {
            int h = lane + 32 * i;
            s += vs[h] * tanh_fast(row[h] + qs[h]);
        }
        #pragma unroll
        for (int o = 16; o; o >>= 1) s += __shfl_xor_sync(0xffffffffu, s, o);
        if (lane == 0) es[p] = s + bv0;
    }
    __syncthreads();

    // softmax over P=196
    float m = -1e30f;
    for (int p = tid; p < PP; p += 256) m = fmaxf(m, es[p]);
    #pragma unroll
    for (int o = 16; o; o >>= 1) m = fmaxf(m, __shfl_xor_sync(0xffffffffu, m, o));
    if (lane == 0) red[warp] = m;
    __syncthreads();
    if (warp == 0) {
        float t = (lane < 8) ? red[lane] : -1e30f;
        #pragma unroll
        for (int o = 4; o; o >>= 1) t = fmaxf(t, __shfl_xor_sync(0xffffffffu, t, o));
        if (lane == 0) red[0] = t;
    }
    __syncthreads();
    m = red[0];
    __syncthreads();

    float sum = 0.0f;
    for (int p = tid; p < PP; p += 256) { float ev = expf(es[p] - m); es[p] = ev; sum += ev; }
    #pragma unroll
    for (int o = 16; o; o >>= 1) sum += __shfl_xor_sync(0xffffffffu, sum, o);
    if (lane == 0) red[warp] = sum;
    __syncthreads();
    if (warp == 0) {
        float t = (lane < 8) ? red[lane] : 0.0f;
        #pragma unroll
        for (int o = 4; o; o >>= 1) t += __shfl_xor_sync(0xffffffffu, t, o);
        if (lane == 0) red[0] = t;
    }
    __syncthreads();
    float inv = 1.0f / red[0];
    for (int p = tid; p < PP; p += 256) {
        float a = es[p] * inv;
        alpha[b * PP + p] = a;
        alpha_out[(size_t)b * (SS * PP) + p] = a;   // base already includes t*P
    }
}

// X[b, H + e] = gate[b,e] * sum_p alpha[b,p] * img[b,p,e]
__global__ void context_kernel(const float* __restrict__ img, const float* __restrict__ alpha,
                               const float* __restrict__ gate, float* __restrict__ X)
{
    __shared__ float al[PP];
    const int b = blockIdx.y;
    const int e = blockIdx.x * 256 + threadIdx.x;
    if (threadIdx.x < PP) al[threadIdx.x] = alpha[b * PP + threadIdx.x];
    __syncthreads();
    const float* ib = img + (size_t)b * PP * EE + e;
    float s0 = 0, s1 = 0, s2 = 0, s3 = 0;
    #pragma unroll 4
    for (int p = 0; p < PP; p += 4) {
        s0 += al[p    ] * ib[(size_t)(p    ) * EE];
        s1 += al[p + 1] * ib[(size_t)(p + 1) * EE];
        s2 += al[p + 2] * ib[(size_t)(p + 2) * EE];
        s3 += al[p + 3] * ib[(size_t)(p + 3) * EE];
    }
    X[b * XK + HH + e] = (s0 + s1 + s2 + s3) * gate[b * EE + e];
}

__global__ void emb_kernel(const float* __restrict__ Wemb, const int* __restrict__ cap,
                           int t, float* __restrict__ X)
{
    int i = blockIdx.x * 256 + threadIdx.x;      // B*H
    int b = i >> 9, h = i & 511;
    int c = cap[b * TT + t];
    X[b * XK + h] = Wemb[(size_t)c * HH + h];
}

__global__ void lstm_kernel(const float* __restrict__ gates, float* __restrict__ c,
                            float* __restrict__ X)
{
    int i = blockIdx.x * 256 + threadIdx.x;      // B*H
    int b = i >> 9, h = i & 511;
    const float* g = gates + (size_t)b * G4;
    float ig = 1.0f / (1.0f + expf(-g[h]));
    float fg = 1.0f / (1.0f + expf(-g[HH + h]));
    float gg = tanhf(g[2 * HH + h]);
    float og = 1.0f / (1.0f + expf(-g[3 * HH + h]));
    float cn = fg * c[i] + ig * gg;
    c[i] = cn;
    X[b * XK + HH + EE + h] = og * tanhf(cn);    // h slice at offset 2560
}

// ---------------- host launch ----------------
extern "C" void kernel_launch(void* const* d_in, const int* in_sizes, int n_in,
                              void* d_out, int out_size)
{
    const float* img   = (const float*)d_in[0];
    const int*   cap   = (const int*)  d_in[1];
    const float* U_att = (const float*)d_in[2];
    const float* bU    = (const float*)d_in[3];
    const float* W_att = (const float*)d_in[4];
    const float* bW    = (const float*)d_in[5];
    const float* v_att = (const float*)d_in[6];
    const float* bv    = (const float*)d_in[7];
    const float* Wih   = (const float*)d_in[8];
    const float* bih   = (const float*)d_in[9];
    const float* Wic   = (const float*)d_in[10];
    const float* bic   = (const float*)d_in[11];
    const float* Wfb   = (const float*)d_in[12];
    const float* bfb   = (const float*)d_in[13];
    const float* Wdo   = (const float*)d_in[14];
    const float* bdo   = (const float*)d_in[15];
    const float* Wemb  = (const float*)d_in[16];
    const float* Wl    = (const float*)d_in[17];
    const float* Ul    = (const float*)d_in[18];
    const float* bl    = (const float*)d_in[19];

    float* preds  = (float*)d_out;                          // [B, 19, V]
    float* alphas = (float*)d_out + (size_t)BB * SS * VV;   // [B, 19, P]

    float *pWs, *pWcat, *pX, *pavg, *pc, *pq, *pgate, *pgates, *palpha;
    cudaGetSymbolAddress((void**)&pWs,    g_Ws);
    cudaGetSymbolAddress((void**)&pWcat,  g_Wcat);
    cudaGetSymbolAddress((void**)&pX,     g_X);
    cudaGetSymbolAddress((void**)&pavg,   g_avg);
    cudaGetSymbolAddress((void**)&pc,     g_c);
    cudaGetSymbolAddress((void**)&pq,     g_q);
    cudaGetSymbolAddress((void**)&pgate,  g_gate);
    cudaGetSymbolAddress((void**)&pgates, g_gates);
    cudaGetSymbolAddress((void**)&palpha, g_alpha);

    // Build Wcat = [Wl ; Ul]  (3072 x 2048)
    {
        int n4a = (2560 * 2048) / 4, n4b = (512 * 2048) / 4;
        copy_kernel<<<(n4a + 255) / 256, 256>>>((const float4*)Wl, (float4*)pWcat, n4a);
        copy_kernel<<<(n4b + 255) / 256, 256>>>((const float4*)Ul,
                                                (float4*)(pWcat + 2560 * 2048), n4b);
    }

    // avg over patches; initial h0 (into X h-slice) and c0
    avg_kernel<<<dim3(EE / 256, BB), 256>>>(img, pavg);
    gemm64<1><<<dim3(HH / 32, BB / 64), 256>>>(pavg, Wih, bih, pX + 2560, HH, EE, EE, XK);
    gemm64<1><<<dim3(HH / 32, BB / 64), 256>>>(pavg, Wic, bic, pc,        HH, EE, EE, HH);

    // W_s = img @ W_att + bW   (25088 x 512, K=2048)
    gemm128<<<dim3(HH / 64, (BB * PP) / 128), 256>>>(img, W_att, bW, pWs, HH, EE, EE, HH);

    for (int t = 0; t < SS; t++) {
        // q = h @ U_att + bU
        gemm64<0><<<dim3(HH / 32, BB / 64), 256>>>(pX + 2560, U_att, bU, pq, HH, HH, XK, HH);
        // alpha = softmax_p( v . tanh(W_s + q) + bv )
        attention_kernel<<<BB, 256>>>(pWs, pq, v_att, bv, palpha, alphas + (size_t)t * PP);
        // gate = sigmoid(h @ Wfb + bfb)
        gemm64<2><<<dim3(EE / 32, BB / 64), 256>>>(pX + 2560, Wfb, bfb, pgate, EE, HH, XK, EE);
        // X[:,512:2560] = gate * (alpha @ img)
        context_kernel<<<dim3(EE / 256, BB), 256>>>(img, palpha, pgate, pX);
        // X[:,0:512] = Wemb[captions[:,t]]
        emb_kernel<<<(BB * HH) / 256, 256>>>(Wemb, cap, t, pX);
        // gates = X @ Wcat + bl   (K = 3072)
        gemm64<0><<<dim3(G4 / 32, BB / 64), 256>>>(pX, pWcat, bl, pgates, G4, XK, XK, G4);
        // LSTM cell: update c, write new h into X[:,2560:]
        lstm_kernel<<<(BB * HH) / 256, 256>>>(pgates, pc, pX);
        // preds[:,t,:] = h_new @ Wdo + bdo   (N=10000, guarded)
        gemm64<0><<<dim3((VV + 31) / 32, BB / 64), 256>>>(pX + 2560, Wdo, bdo,
                                                          preds + (size_t)t * VV,
                                                          VV, HH, XK, SS * VV);
    }
}

// round 2
// speedup vs baseline: 1.0041x; 1.0041x over previous
#include <cuda_runtime.h>
#include <math.h>

// Problem dims
#define BB 128
#define PP 196
#define EE 2048
#define HH 512
#define VV 10000
#define TT 20
#define SS 19            // decode steps = T-1
#define XK 3072          // H + E + H  (concat input for fused gates GEMM)
#define G4 2048          // 4*H

// ---------------- scratch (device globals; no allocation allowed) ----------------
__device__ float g_Ws[(size_t)BB * PP * HH];    // 51.4 MB  precomputed img@W_att + bW
__device__ float g_Wcat[(size_t)XK * G4];       // 25.2 MB  [Wl ; Ul]
__device__ float g_X[BB * XK];                  // [emb | gate*ctx | h]
__device__ float g_avg[BB * EE];
__device__ float g_c[BB * HH];
__device__ float g_q[BB * HH];
__device__ float g_gate[BB * EE];
__device__ float g_gates[BB * G4];
__device__ float g_alpha[BB * PP];

// ---------------- fast-math helpers ----------------
__device__ __forceinline__ float ex2f(float x) { float r; asm("ex2.approx.f32 %0,%1;" : "=f"(r) : "f"(x)); return r; }
__device__ __forceinline__ float rcpf(float x) { float r; asm("rcp.approx.f32 %0,%1;" : "=f"(r) : "f"(x)); return r; }
// tanh via ex2+rcp: rel err ~1e-7 (used only in the hot attention loop)
__device__ __forceinline__ float tanh_fast(float x) {
    float ax = fabsf(x);
    float e  = ex2f(ax * -2.8853900817779268f);   // exp(-2|x|)
    float r  = (1.0f - e) * rcpf(1.0f + e);
    return copysignf(r, x);
}

// ---------------- generic fp32 GEMM, BM=64 BN=32 BK=16, 256 thr, 4x2 microtile ----
// C[M,N] = act(A[M,K] @ W[K,N] + bias[N]) ; M % 64 == 0 ; K % 16 == 0 ; N guarded
// ACT: 0 = none, 1 = tanh (accurate), 2 = sigmoid (accurate)
template <int ACT>
__global__ void __launch_bounds__(256)
gemm64(const float* __restrict__ A, const float* __restrict__ W,
       const float* __restrict__ bias, float* __restrict__ C,
       int N, int K, int lda, int ldc)
{
    __shared__ float As[16][68];   // transposed A tile, padded
    __shared__ float Bs[16][32];
    const int m0  = blockIdx.y * 64;
    const int n0  = blockIdx.x * 32;
    const int tid = threadIdx.x;
    const int tx  = tid & 15, ty = tid >> 4;

    float acc[4][2] = {};
    const int ar = tid >> 2;            // 0..63  (A row within tile)
    const int ak = (tid & 3) << 2;      // 0,4,8,12 (k offset, float4)
    const int wr = tid >> 4;            // 0..15 (W k-row)
    const int wc = (tid & 15) << 1;     // 0..30 (W col pair)

    const float* Ag = A + (size_t)(m0 + ar) * lda + ak;

    for (int k0 = 0; k0 < K; k0 += 16) {
        float4 av = *(const float4*)(Ag + k0);
        As[ak + 0][ar] = av.x; As[ak + 1][ar] = av.y;
        As[ak + 2][ar] = av.z; As[ak + 3][ar] = av.w;

        int wn = n0 + wc;
        float2 wv;
        wv.x = (wn     < N) ? W[(size_t)(k0 + wr) * N + wn    ] : 0.0f;
        wv.y = (wn + 1 < N) ? W[(size_t)(k0 + wr) * N + wn + 1] : 0.0f;
        Bs[wr][wc] = wv.x; Bs[wr][wc + 1] = wv.y;
        __syncthreads();

        #pragma unroll
        for (int kk = 0; kk < 16; kk++) {
            float4 a = *(const float4*)&As[kk][ty << 2];
            float  w0 = Bs[kk][tx << 1], w1 = Bs[kk][(tx << 1) + 1];
            acc[0][0] += a.x * w0; acc[0][1] += a.x * w1;
            acc[1][0] += a.y * w0; acc[1][1] += a.y * w1;
            acc[2][0] += a.z * w0; acc[2][1] += a.z * w1;
            acc[3][0] += a.w * w0; acc[3][1] += a.w * w1;
        }
        __syncthreads();
    }

    #pragma unroll
    for (int i = 0; i < 4; i++) {
        int m = m0 + (ty << 2) + i;
        #pragma unroll
        for (int j = 0; j < 2; j++) {
            int n = n0 + (tx << 1) + j;
            if (n < N) {
                float v = acc[i][j] + bias[n];
                if (ACT == 1)      v = tanhf(v);
                else if (ACT == 2) v = 1.0f / (1.0f + expf(-v));
                C[(size_t)m * ldc + n] = v;
            }
        }
    }
}

// ---------------- big GEMM for W_s precompute: BM=128 BN=64 BK=16, 8x4 microtile --
// Requirements: M%128==0, N%64==0, K%16==0 (W_s: 25088 x 512, K=2048)
__global__ void __launch_bounds__(256)
gemm128(const float* __restrict__ A, const float* __restrict__ W,
        const float* __restrict__ bias, float* __restrict__ C,
        int N, int K, int lda, int ldc)
{
    __shared__ float As[16][132];
    __shared__ float Bs[16][64];
    const int m0  = blockIdx.y * 128;
    const int n0  = blockIdx.x * 64;
    const int tid = threadIdx.x;
    const int tx  = tid & 15, ty = tid >> 4;

    float acc[8][4] = {};
    const int ar = tid >> 1;           // 0..127
    const int ak = (tid & 1) << 3;     // 0 or 8
    const int wr = tid >> 4;           // 0..15
    const int wc = (tid & 15) << 2;    // 0..60

    const float* Ag = A + (size_t)(m0 + ar) * lda + ak;

    for (int k0 = 0; k0 < K; k0 += 16) {
        float4 a0 = *(const float4*)(Ag + k0);
        float4 a1 = *(const float4*)(Ag + k0 + 4);
        As[ak + 0][ar] = a0.x; As[ak + 1][ar] = a0.y; As[ak + 2][ar] = a0.z; As[ak + 3][ar] = a0.w;
        As[ak + 4][ar] = a1.x; As[ak + 5][ar] = a1.y; As[ak + 6][ar] = a1.z; As[ak + 7][ar] = a1.w;

        float4 wv = *(const float4*)(W + (size_t)(k0 + wr) * N + n0 + wc);
        *(float4*)&Bs[wr][wc] = wv;
        __syncthreads();

        #pragma unroll
        for (int kk = 0; kk < 16; kk++) {
            float a[8], w[4];
            *(float4*)&a[0] = *(const float4*)&As[kk][ty << 3];
            *(float4*)&a[4] = *(const float4*)&As[kk][(ty << 3) + 4];
            *(float4*)&w[0] = *(const float4*)&Bs[kk][tx << 2];
            #pragma unroll
            for (int i = 0; i < 8; i++)
                #pragma unroll
                for (int j = 0; j < 4; j++)
                    acc[i][j] += a[i] * w[j];
        }
        __syncthreads();
    }

    #pragma unroll
    for (int i = 0; i < 8; i++) {
        int m = m0 + (ty << 3) + i;
        #pragma unroll
        for (int j = 0; j < 4; j++) {
            int n = n0 + (tx << 2) + j;
            C[(size_t)m * ldc + n] = acc[i][j] + bias[n];
        }
    }
}

// ---------------- small kernels ----------------
__global__ void copy_kernel(const float4* __restrict__ src, float4* __restrict__ dst, int n4)
{
    int i = blockIdx.x * 256 + threadIdx.x;
    if (i < n4) dst[i] = src[i];
}

__global__ void avg_kernel(const float* __restrict__ img, float* __restrict__ avg)
{
    int b = blockIdx.y;
    int e = blockIdx.x * 256 + threadIdx.x;
    const float* ib = img + (size_t)b * PP * EE + e;
    float s0 = 0, s1 = 0, s2 = 0, s3 = 0;
    #pragma unroll 4
    for (int p = 0; p < PP; p += 4) {
        s0 += ib[(size_t)(p    ) * EE];
        s1 += ib[(size_t)(p + 1) * EE];
        s2 += ib[(size_t)(p + 2) * EE];
        s3 += ib[(size_t)(p + 3) * EE];
    }
    avg[b * EE + e] = (s0 + s1 + s2 + s3) * (1.0f / PP);
}

// e[b,p] = sum_h v[h]*tanh(Ws[b,p,h]+q[b,h]) + bv ; alpha = softmax_p(e)
__global__ void __launch_bounds__(256)
attention_kernel(const float* __restrict__ Ws, const float* __restrict__ q,
                 const float* __restrict__ v_att, const float* __restrict__ bv,
                 float* __restrict__ alpha, float* __restrict__ alpha_out)
{
    __shared__ float qs[HH], vs[HH], es[PP], red[8];
    const int b = blockIdx.x;
    const int tid = threadIdx.x;
    const int lane = tid & 31, warp = tid >> 5;

    for (int i = tid; i < HH; i += 256) { qs[i] = q[b * HH + i]; vs[i] = v_att[i]; }
    __syncthreads();

    const float* Wb = Ws + (size_t)b * PP * HH;
    const float bv0 = bv[0];

    for (int p = warp; p < PP; p += 8) {
        const float* row = Wb + (size_t)p * HH;
        float s = 0.0f;
        #pragma unroll
        for (int i = 0; i < HH / 32; i++) {
            int h = lane + 32 * i;
            s += vs[h] * tanh_fast(row[h] + qs[h]);
        }
        #pragma unroll
        for (int o = 16; o; o >>= 1) s += __shfl_xor_sync(0xffffffffu, s, o);
        if (lane == 0) es[p] = s + bv0;
    }
    __syncthreads();

    // softmax over P=196
    float m = -1e30f;
    for (int p = tid; p < PP; p += 256) m = fmaxf(m, es[p]);
    #pragma unroll
    for (int o = 16; o; o >>= 1) m = fmaxf(m, __shfl_xor_sync(0xffffffffu, m, o));
    if (lane == 0) red[warp] = m;
    __syncthreads();
    if (warp == 0) {
        float t = (lane < 8) ? red[lane] : -1e30f;
        #pragma unroll
        for (int o = 4; o; o >>= 1) t = fmaxf(t, __shfl_xor_sync(0xffffffffu, t, o));
        if (lane == 0) red[0] = t;
    }
    __syncthreads();
    m = red[0];
    __syncthreads();

    float sum = 0.0f;
    for (int p = tid; p < PP; p += 256) { float ev = expf(es[p] - m); es[p] = ev; sum += ev; }
    #pragma unroll
    for (int o = 16; o; o >>= 1) sum += __shfl_xor_sync(0xffffffffu, sum, o);
    if (lane == 0) red[warp] = sum;
    __syncthreads();
    if (warp == 0) {
        float t = (lane < 8) ? red[lane] : 0.0f;
        #pragma unroll
        for (int o = 4; o; o >>= 1) t += __shfl_xor_sync(0xffffffffu, t, o);
        if (lane == 0) red[0] = t;
    }
    __syncthreads();
    float inv = 1.0f / red[0];
    for (int p = tid; p < PP; p += 256) {
        float a = es[p] * inv;
        alpha[b * PP + p] = a;
        alpha_out[(size_t)b * (SS * PP) + p] = a;   // base already includes t*P
    }
}

// X[b, H + e] = gate[b,e] * sum_p alpha[b,p] * img[b,p,e]
__global__ void context_kernel(const float* __restrict__ img, const float* __restrict__ alpha,
                               const float* __restrict__ gate, float* __restrict__ X)
{
    __shared__ float al[PP];
    const int b = blockIdx.y;
    const int e = blockIdx.x * 256 + threadIdx.x;
    if (threadIdx.x < PP) al[threadIdx.x] = alpha[b * PP + threadIdx.x];
    __syncthreads();
    const float* ib = img + (size_t)b * PP * EE + e;
    float s0 = 0, s1 = 0, s2 = 0, s3 = 0;
    #pragma unroll 4
    for (int p = 0; p < PP; p += 4) {
        s0 += al[p    ] * ib[(size_t)(p    ) * EE];
        s1 += al[p + 1] * ib[(size_t)(p + 1) * EE];
        s2 += al[p + 2] * ib[(size_t)(p + 2) * EE];
        s3 += al[p + 3] * ib[(size_t)(p + 3) * EE];
    }
    X[b * XK + HH + e] = (s0 + s1 + s2 + s3) * gate[b * EE + e];
}

__global__ void emb_kernel(const float* __restrict__ Wemb, const int* __restrict__ cap,
                           int t, float* __restrict__ X)
{
    int i = blockIdx.x * 256 + threadIdx.x;      // B*H
    int b = i >> 9, h = i & 511;
    int c = cap[b * TT + t];
    X[b * XK + h] = Wemb[(size_t)c * HH + h];
}

__global__ void lstm_kernel(const float* __restrict__ gates, float* __restrict__ c,
                            float* __restrict__ X)
{
    int i = blockIdx.x * 256 + threadIdx.x;      // B*H
    int b = i >> 9, h = i & 511;
    const float* g = gates + (size_t)b * G4;
    float ig = 1.0f / (1.0f + expf(-g[h]));
    float fg = 1.0f / (1.0f + expf(-g[HH + h]));
    float gg = tanhf(g[2 * HH + h]);
    float og = 1.0f / (1.0f + expf(-g[3 * HH + h]));
    float cn = fg * c[i] + ig * gg;
    c[i] = cn;
    X[b * XK + HH + EE + h] = og * tanhf(cn);    // h slice at offset 2560
}

// ---------------- host launch ----------------
extern "C" void kernel_launch(void* const* d_in, const int* in_sizes, int n_in,
                              void* d_out, int out_size)
{
    const float* img   = (const float*)d_in[0];
    const int*   cap   = (const int*)  d_in[1];
    const float* U_att = (const float*)d_in[2];
    const float* bU    = (const float*)d_in[3];
    const float* W_att = (const float*)d_in[4];
    const float* bW    = (const float*)d_in[5];
    const float* v_att = (const float*)d_in[6];
    const float* bv    = (const float*)d_in[7];
    const float* Wih   = (const float*)d_in[8];
    const float* bih   = (const float*)d_in[9];
    const float* Wic   = (const float*)d_in[10];
    const float* bic   = (const float*)d_in[11];
    const float* Wfb   = (const float*)d_in[12];
    const float* bfb   = (const float*)d_in[13];
    const float* Wdo   = (const float*)d_in[14];
    const float* bdo   = (const float*)d_in[15];
    const float* Wemb  = (const float*)d_in[16];
    const float* Wl    = (const float*)d_in[17];
    const float* Ul    = (const float*)d_in[18];
    const float* bl    = (const float*)d_in[19];

    float* preds  = (float*)d_out;                          // [B, 19, V]
    float* alphas = (float*)d_out + (size_t)BB * SS * VV;   // [B, 19, P]

    float *pWs, *pWcat, *pX, *pavg, *pc, *pq, *pgate, *pgates, *palpha;
    cudaGetSymbolAddress((void**)&pWs,    g_Ws);
    cudaGetSymbolAddress((void**)&pWcat,  g_Wcat);
    cudaGetSymbolAddress((void**)&pX,     g_X);
    cudaGetSymbolAddress((void**)&pavg,   g_avg);
    cudaGetSymbolAddress((void**)&pc,     g_c);
    cudaGetSymbolAddress((void**)&pq,     g_q);
    cudaGetSymbolAddress((void**)&pgate,  g_gate);
    cudaGetSymbolAddress((void**)&pgates, g_gates);
    cudaGetSymbolAddress((void**)&palpha, g_alpha);

    // Build Wcat = [Wl ; Ul]  (3072 x 2048)
    {
        int n4a = (2560 * 2048) / 4, n4b = (512 * 2048) / 4;
        copy_kernel<<<(n4a + 255) / 256, 256>>>((const float4*)Wl, (float4*)pWcat, n4a);
        copy_kernel<<<(n4b + 255) / 256, 256>>>((const float4*)Ul,
                                                (float4*)(pWcat + 2560 * 2048), n4b);
    }

    // avg over patches; initial h0 (into X h-slice) and c0
    avg_kernel<<<dim3(EE / 256, BB), 256>>>(img, pavg);
    gemm64<1><<<dim3(HH / 32, BB / 64), 256>>>(pavg, Wih, bih, pX + 2560, HH, EE, EE, XK);
    gemm64<1><<<dim3(HH / 32, BB / 64), 256>>>(pavg, Wic, bic, pc,        HH, EE, EE, HH);

    // W_s = img @ W_att + bW   (25088 x 512, K=2048)
    gemm128<<<dim3(HH / 64, (BB * PP) / 128), 256>>>(img, W_att, bW, pWs, HH, EE, EE, HH);

    for (int t = 0; t < SS; t++) {
        // q = h @ U_att + bU
        gemm64<0><<<dim3(HH / 32, BB / 64), 256>>>(pX + 2560, U_att, bU, pq, HH, HH, XK, HH);
        // alpha = softmax_p( v . tanh(W_s + q) + bv )
        attention_kernel<<<BB, 256>>>(pWs, pq, v_att, bv, palpha, alphas + (size_t)t * PP);
        // gate = sigmoid(h @ Wfb + bfb)
        gemm64<2><<<dim3(EE / 32, BB / 64), 256>>>(pX + 2560, Wfb, bfb, pgate, EE, HH, XK, EE);
        // X[:,512:2560] = gate * (alpha @ img)
        context_kernel<<<dim3(EE / 256, BB), 256>>>(img, palpha, pgate, pX);
        // X[:,0:512] = Wemb[captions[:,t]]
        emb_kernel<<<(BB * HH) / 256, 256>>>(Wemb, cap, t, pX);
        // gates = X @ Wcat + bl   (K = 3072)
        gemm64<0><<<dim3(G4 / 32, BB / 64), 256>>>(pX, pWcat, bl, pgates, G4, XK, XK, G4);
        // LSTM cell: update c, write new h into X[:,2560:]
        lstm_kernel<<<(BB * HH) / 256, 256>>>(pgates, pc, pX);
        // preds[:,t,:] = h_new @ Wdo + bdo   (N=10000, guarded)
        gemm64<0><<<dim3((VV + 31) / 32, BB / 64), 256>>>(pX + 2560, Wdo, bdo,
                                                          preds + (size_t)t * VV,
                                                          VV, HH, XK, SS * VV);
    }
}

// round 5
// speedup vs baseline: 1.3152x; 1.3099x over previous
#include <cuda_runtime.h>
#include <cuda_bf16.h>
#include <math.h>
#include <stdint.h>

#define BB 128
#define PP 196
#define EE 2048
#define HH 512
#define VV 10000
#define VPAD 10112
#define TT 20
#define SS 19
#define XK 3072
#define G4 2048

typedef __nv_bfloat16 bf16;

// ---------------- device global scratch ----------------
__device__ bf16  g_imgh[(size_t)BB * PP * EE];
__device__ bf16  g_imgl[(size_t)BB * PP * EE];
__device__ float g_Ws[(size_t)BB * PP * HH];
__device__ bf16  g_BWatt_h[HH * EE],  g_BWatt_l[HH * EE];
__device__ bf16  g_BWih_h[HH * EE],   g_BWih_l[HH * EE];
__device__ bf16  g_BWic_h[HH * EE],   g_BWic_l[HH * EE];
__device__ bf16  g_BUatt_h[HH * HH],  g_BUatt_l[HH * HH];
__device__ bf16  g_BWfb_h[EE * HH],   g_BWfb_l[EE * HH];
__device__ bf16  g_BWcat_h[(size_t)G4 * XK], g_BWcat_l[(size_t)G4 * XK];
__device__ bf16  g_BWdo_h[(size_t)VPAD * HH], g_BWdo_l[(size_t)VPAD * HH];
__device__ bf16  g_avgh[BB * EE], g_avgl[BB * EE];
__device__ bf16  g_Xh[BB * XK],   g_Xl[BB * XK];
__device__ float g_avg[BB * EE];
__device__ float g_c[BB * HH];
__device__ float g_q[BB * HH];
__device__ float g_gate[BB * EE];
__device__ float g_gates[BB * G4];
__device__ float g_alpha[BB * PP];

// ---------------- helpers ----------------
__device__ __forceinline__ uint32_t s2u(const void* p) {
    uint32_t a;
    asm("{ .reg .u64 t; cvta.to.shared.u64 t, %1; cvt.u32.u64 %0, t; }" : "=r"(a) : "l"(p));
    return a;
}
__device__ __forceinline__ void cp16(uint32_t s, const void* g) {
    asm volatile("cp.async.cg.shared.global [%0], [%1], 16;" :: "r"(s), "l"(g) : "memory");
}
__device__ __forceinline__ void cp_commit() { asm volatile("cp.async.commit_group;" ::: "memory"); }
template <int N> __device__ __forceinline__ void cp_wait() {
    asm volatile("cp.async.wait_group %0;" :: "n"(N) : "memory");
}
__device__ __forceinline__ void ldsm4(uint32_t* r, uint32_t addr) {
    asm volatile("ldmatrix.sync.aligned.m8n8.x4.shared.b16 {%0,%1,%2,%3}, [%4];"
                 : "=r"(r[0]), "=r"(r[1]), "=r"(r[2]), "=r"(r[3]) : "r"(addr));
}
__device__ __forceinline__ void mma16816(float* d, const uint32_t* a, const uint32_t* b) {
    asm volatile("mma.sync.aligned.m16n8k16.row.col.f32.bf16.bf16.f32 "
                 "{%0,%1,%2,%3}, {%4,%5,%6,%7}, {%8,%9}, {%0,%1,%2,%3};"
                 : "+f"(d[0]), "+f"(d[1]), "+f"(d[2]), "+f"(d[3])
                 : "r"(a[0]), "r"(a[1]), "r"(a[2]), "r"(a[3]), "r"(b[0]), "r"(b[1]));
}
__device__ __forceinline__ float ex2f(float x) { float r; asm("ex2.approx.f32 %0,%1;" : "=f"(r) : "f"(x)); return r; }
__device__ __forceinline__ float rcpf(float x) { float r; asm("rcp.approx.f32 %0,%1;" : "=f"(r) : "f"(x)); return r; }
__device__ __forceinline__ float tanh_fast(float x) {
    float ax = fabsf(x);
    float e  = ex2f(ax * -2.8853900817779268f);
    float r  = (1.0f - e) * rcpf(1.0f + e);
    return copysignf(r, x);
}
__device__ __forceinline__ void split2(float v, bf16* ph, bf16* pl) {
    bf16 h = __float2bfloat16(v);
    *ph = h;
    *pl = __float2bfloat16(v - __bfloat162float(h));
}

// ---------------- split-bf16 HMMA GEMM ----------------
// C[M,Nstore] = act(A @ B^T + bias)
// A: (Ah,Al)[M,K] bf16 row stride lda.  B: (Bh,Bl)[Npad,K] bf16 row stride K.
// CTA tile 128x128, BK=32, 8 warps (2M x 4N), warp tile 64x32.
// SMEM: per buffer 4 tiles (Ah,Al,Bh,Bl) of 128 rows x 80B (32 bf16 + 8 pad).
#define TILE_B   10240          // 128 * 80
#define BUF_B    40960          // 4 tiles
#define SMEM_SZ  81920          // 2 buffers

template <int ACT>
__global__ void __launch_bounds__(256, 1)
tc_gemm(const bf16* __restrict__ Ah, const bf16* __restrict__ Al, int lda,
        const bf16* __restrict__ Bh, const bf16* __restrict__ Bl,
        const float* __restrict__ bias, float* __restrict__ C, int ldc,
        int Nstore, int K)
{
    extern __shared__ char sm[];
    const int tid = threadIdx.x, lane = tid & 31, wid = tid >> 5;
    const int m0 = blockIdx.y << 7, n0 = blockIdx.x << 7;
    const int wy = wid & 1, wx = wid >> 1;     // warp 64-row band, 32-col band
    const uint32_t sb = s2u(sm);

    const char* gAh = (const char*)(Ah + (size_t)m0 * lda);
    const char* gAl = (const char*)(Al + (size_t)m0 * lda);
    const char* gBh = (const char*)(Bh + (size_t)n0 * K);
    const char* gBl = (const char*)(Bl + (size_t)n0 * K);
    const size_t strA = (size_t)lda * 2, strB = (size_t)K * 2;

    // ldmatrix per-lane offsets
    const int arow = lane & 15;
    const int acol = (lane >> 4) << 4;                       // 0 or 16 bytes
    const int brow = ((lane >> 4) << 3) + (lane & 7);
    const int bcol = ((lane >> 3) & 1) << 4;
    const uint32_t aoff = (uint32_t)((wy * 64 + arow) * 80 + acol);
    const uint32_t boff = (uint32_t)((wx * 32 + brow) * 80 + bcol);

    float acc[4][4][4] = {};

    const int nk = K >> 5;

    auto issue = [&](int ch, int buf) {
        const int k0b = ch << 6;                 // 32 bf16 = 64 bytes
        const uint32_t s0 = sb + buf * BUF_B;
        #pragma unroll
        for (int half = 0; half < 2; half++) {
            int u  = tid + half * 256;
            int r  = u >> 2;
            int sg = (u & 3) << 4;
            uint32_t s = s0 + r * 80 + sg;
            size_t gA = (size_t)r * strA + k0b + sg;
            size_t gB = (size_t)r * strB + k0b + sg;
            cp16(s,              gAh + gA);
            cp16(s + TILE_B,     gAl + gA);
            cp16(s + 2 * TILE_B, gBh + gB);
            cp16(s + 3 * TILE_B, gBl + gB);
        }
        cp_commit();
    };

    issue(0, 0);
    if (nk > 1) issue(1, 1);

    for (int ch = 0; ch < nk; ch++) {
        // depth-2 prefetch: leave at most 1 group in flight so chunk ch's
        // buffer is complete before we read it.
        if (ch + 2 < nk) { cp_wait<1>(); } else { cp_wait<0>(); }
        __syncthreads();

        const uint32_t base = sb + (ch & 1) * BUF_B;
        #pragma unroll
        for (int ks = 0; ks < 2; ks++) {
            uint32_t ah[4][4], al[4][4];
            #pragma unroll
            for (int mi = 0; mi < 4; mi++) {
                uint32_t o = aoff + mi * (16 * 80) + ks * 32;
                ldsm4(ah[mi], base + o);
                ldsm4(al[mi], base + TILE_B + o);
            }
            uint32_t bh[2][4], bl[2][4];
            #pragma unroll
            for (int nj = 0; nj < 2; nj++) {
                uint32_t o = boff + nj * (16 * 80) + ks * 32;
                ldsm4(bh[nj], base + 2 * TILE_B + o);
                ldsm4(bl[nj], base + 3 * TILE_B + o);
            }
            #pragma unroll
            for (int mi = 0; mi < 4; mi++) {
                #pragma unroll
                for (int n8 = 0; n8 < 4; n8++) {
                    const uint32_t* pbh = &bh[n8 >> 1][(n8 & 1) << 1];
                    const uint32_t* pbl = &bl[n8 >> 1][(n8 & 1) << 1];
                    mma16816(acc[mi][n8], ah[mi], pbh);
                    mma16816(acc[mi][n8], ah[mi], pbl);
                    mma16816(acc[mi][n8], al[mi], pbh);
                }
            }
        }
        __syncthreads();
        if (ch + 2 < nk) issue(ch + 2, ch & 1);
    }

    // epilogue
    #pragma unroll
    for (int mi = 0; mi < 4; mi++) {
        #pragma unroll
        for (int n8 = 0; n8 < 4; n8++) {
            int mb = m0 + wy * 64 + mi * 16 + (lane >> 2);
            int nb = n0 + wx * 32 + n8 * 8 + ((lane & 3) << 1);
            #pragma unroll
            for (int g = 0; g < 2; g++) {
                int m = mb + g * 8;
                #pragma unroll
                for (int j = 0; j < 2; j++) {
                    int n = nb + j;
                    if (n < Nstore) {
                        float v = acc[mi][n8][g * 2 + j] + bias[n];
                        if (ACT == 1)      v = tanhf(v);
                        else if (ACT == 2) v = 1.0f / (1.0f + expf(-v));
                        C[(size_t)m * ldc + n] = v;
                    }
                }
            }
        }
    }
}

// ---------------- conversion kernels ----------------
__global__ void split_kernel(const float* __restrict__ src, bf16* __restrict__ dh,
                             bf16* __restrict__ dl, int n)
{
    int i = blockIdx.x * 256 + threadIdx.x;
    if (i < n) split2(src[i], dh + i, dl + i);
}

// src [Ksrc, N] fp32 -> transposed split dst[n*dst_ld + koff + k]
__global__ void tsplit_kernel(const float* __restrict__ src, bf16* __restrict__ dh,
                              bf16* __restrict__ dl, int Ksrc, int N, int dst_ld, int koff)
{
    __shared__ float t[32][33];
    const int n0 = blockIdx.x << 5, k0 = blockIdx.y << 5;
    #pragma unroll
    for (int j = 0; j < 4; j++) {
        int kk = k0 + threadIdx.y + (j << 3);
        int n  = n0 + threadIdx.x;
        t[threadIdx.y + (j << 3)][threadIdx.x] = (n < N) ? src[(size_t)kk * N + n] : 0.0f;
    }
    __syncthreads();
    #pragma unroll
    for (int j = 0; j < 4; j++) {
        int nn = n0 + threadIdx.y + (j << 3);
        int k  = k0 + threadIdx.x;
        size_t o = (size_t)nn * dst_ld + koff + k;
        split2(t[threadIdx.x][threadIdx.y + (j << 3)], dh + o, dl + o);
    }
}

__global__ void splitH_kernel(const float* __restrict__ src, bf16* __restrict__ Xh,
                              bf16* __restrict__ Xl)
{
    int i = blockIdx.x * 256 + threadIdx.x;
    int b = i >> 9, h = i & 511;
    split2(src[i], Xh + (size_t)b * XK + 2560 + h, Xl + (size_t)b * XK + 2560 + h);
}

// ---------------- pointwise / attention kernels ----------------
__global__ void avg_kernel(const float* __restrict__ img, float* __restrict__ avg,
                           bf16* __restrict__ ah, bf16* __restrict__ al)
{
    int b = blockIdx.y;
    int e = blockIdx.x * 256 + threadIdx.x;
    const float* ib = img + (size_t)b * PP * EE + e;
    float s = 0;
    #pragma unroll 4
    for (int p = 0; p < PP; p++) s += ib[(size_t)p * EE];
    float v = s * (1.0f / PP);
    avg[b * EE + e] = v;
    split2(v, ah + b * EE + e, al + b * EE + e);
}

__global__ void __launch_bounds__(256)
attention_kernel(const float* __restrict__ Ws, const float* __restrict__ q,
                 const float* __restrict__ v_att, const float* __restrict__ bv,
                 float* __restrict__ alpha, float* __restrict__ alpha_out)
{
    __shared__ float qs[HH], vs[HH], es[PP], red[8];
    const int b = blockIdx.x, tid = threadIdx.x;
    const int lane = tid & 31, warp = tid >> 5;

    for (int i = tid; i < HH; i += 256) { qs[i] = q[b * HH + i]; vs[i] = v_att[i]; }
    __syncthreads();

    const float* Wb = Ws + (size_t)b * PP * HH;
    const float bv0 = bv[0];
    for (int p = warp; p < PP; p += 8) {
        const float* row = Wb + (size_t)p * HH;
        float s = 0.0f;
        #pragma unroll
        for (int i = 0; i < HH / 32; i++) {
            int h = lane + 32 * i;
            s += vs[h] * tanh_fast(row[h] + qs[h]);
        }
        #pragma unroll
        for (int o = 16; o; o >>= 1) s += __shfl_xor_sync(0xffffffffu, s, o);
        if (lane == 0) es[p] = s + bv0;
    }
    __syncthreads();

    float m = -1e30f;
    for (int p = tid; p < PP; p += 256) m = fmaxf(m, es[p]);
    #pragma unroll
    for (int o = 16; o; o >>= 1) m = fmaxf(m, __shfl_xor_sync(0xffffffffu, m, o));
    if (lane == 0) red[warp] = m;
    __syncthreads();
    if (warp == 0) {
        float t = (lane < 8) ? red[lane] : -1e30f;
        #pragma unroll
        for (int o = 4; o; o >>= 1) t = fmaxf(t, __shfl_xor_sync(0xffffffffu, t, o));
        if (lane == 0) red[0] = t;
    }
    __syncthreads();
    m = red[0];
    __syncthreads();

    float sum = 0.0f;
    for (int p = tid; p < PP; p += 256) { float ev = expf(es[p] - m); es[p] = ev; sum += ev; }
    #pragma unroll
    for (int o = 16; o; o >>= 1) sum += __shfl_xor_sync(0xffffffffu, sum, o);
    if (lane == 0) red[warp] = sum;
    __syncthreads();
    if (warp == 0) {
        float t = (lane < 8) ? red[lane] : 0.0f;
        #pragma unroll
        for (int o = 4; o; o >>= 1) t += __shfl_xor_sync(0xffffffffu, t, o);
        if (lane == 0) red[0] = t;
    }
    __syncthreads();
    float inv = 1.0f / red[0];
    for (int p = tid; p < PP; p += 256) {
        float a = es[p] * inv;
        alpha[b * PP + p] = a;
        alpha_out[(size_t)b * (SS * PP) + p] = a;
    }
}

__global__ void context_kernel(const float* __restrict__ img, const float* __restrict__ alpha,
                               const float* __restrict__ gate,
                               bf16* __restrict__ Xh, bf16* __restrict__ Xl)
{
    __shared__ float al[PP];
    const int b = blockIdx.y;
    const int e = blockIdx.x * 256 + threadIdx.x;
    if (threadIdx.x < PP) al[threadIdx.x] = alpha[b * PP + threadIdx.x];
    __syncthreads();
    const float* ib = img + (size_t)b * PP * EE + e;
    float s0 = 0, s1 = 0, s2 = 0, s3 = 0;
    #pragma unroll 4
    for (int p = 0; p < PP; p += 4) {
        s0 += al[p    ] * ib[(size_t)(p    ) * EE];
        s1 += al[p + 1] * ib[(size_t)(p + 1) * EE];
        s2 += al[p + 2] * ib[(size_t)(p + 2) * EE];
        s3 += al[p + 3] * ib[(size_t)(p + 3) * EE];
    }
    float v = (s0 + s1 + s2 + s3) * gate[b * EE + e];
    size_t o = (size_t)b * XK + HH + e;
    split2(v, Xh + o, Xl + o);
}

__global__ void emb_kernel(const float* __restrict__ Wemb, const int* __restrict__ cap,
                           int t, bf16* __restrict__ Xh, bf16* __restrict__ Xl)
{
    int i = blockIdx.x * 256 + threadIdx.x;
    int b = i >> 9, h = i & 511;
    int c = cap[b * TT + t];
    size_t o = (size_t)b * XK + h;
    split2(Wemb[(size_t)c * HH + h], Xh + o, Xl + o);
}

__global__ void lstm_kernel(const float* __restrict__ gates, float* __restrict__ c,
                            bf16* __restrict__ Xh, bf16* __restrict__ Xl)
{
    int i = blockIdx.x * 256 + threadIdx.x;
    int b = i >> 9, h = i & 511;
    const float* g = gates + (size_t)b * G4;
    float ig = 1.0f / (1.0f + expf(-g[h]));
    float fg = 1.0f / (1.0f + expf(-g[HH + h]));
    float gg = tanhf(g[2 * HH + h]);
    float og = 1.0f / (1.0f + expf(-g[3 * HH + h]));
    float cn = fg * c[i] + ig * gg;
    c[i] = cn;
    size_t o = (size_t)b * XK + 2560 + h;
    split2(og * tanhf(cn), Xh + o, Xl + o);
}

// ---------------- host launch ----------------
extern "C" void kernel_launch(void* const* d_in, const int* in_sizes, int n_in,
                              void* d_out, int out_size)
{
    const float* img   = (const float*)d_in[0];
    const int*   cap   = (const int*)  d_in[1];
    const float* U_att = (const float*)d_in[2];
    const float* bU    = (const float*)d_in[3];
    const float* W_att = (const float*)d_in[4];
    const float* bW    = (const float*)d_in[5];
    const float* v_att = (const float*)d_in[6];
    const float* bv    = (const float*)d_in[7];
    const float* Wih   = (const float*)d_in[8];
    const float* bih   = (const float*)d_in[9];
    const float* Wic   = (const float*)d_in[10];
    const float* bic   = (const float*)d_in[11];
    const float* Wfb   = (const float*)d_in[12];
    const float* bfb   = (const float*)d_in[13];
    const float* Wdo   = (const float*)d_in[14];
    const float* bdo   = (const float*)d_in[15];
    const float* Wemb  = (const float*)d_in[16];
    const float* Wl    = (const float*)d_in[17];
    const float* Ul    = (const float*)d_in[18];
    const float* bl    = (const float*)d_in[19];

    float* preds  = (float*)d_out;
    float* alphas = (float*)d_out + (size_t)BB * SS * VV;

    bf16 *imgh, *imgl, *BWatt_h, *BWatt_l, *BWih_h, *BWih_l, *BWic_h, *BWic_l;
    bf16 *BUatt_h, *BUatt_l, *BWfb_h, *BWfb_l, *BWcat_h, *BWcat_l, *BWdo_h, *BWdo_l;
    bf16 *avgh, *avgl, *Xh, *Xl;
    float *pWs, *pavg, *pc, *pq, *pgate, *pgates, *palpha;
    cudaGetSymbolAddress((void**)&imgh, g_imgh);     cudaGetSymbolAddress((void**)&imgl, g_imgl);
    cudaGetSymbolAddress((void**)&BWatt_h, g_BWatt_h); cudaGetSymbolAddress((void**)&BWatt_l, g_BWatt_l);
    cudaGetSymbolAddress((void**)&BWih_h, g_BWih_h); cudaGetSymbolAddress((void**)&BWih_l, g_BWih_l);
    cudaGetSymbolAddress((void**)&BWic_h, g_BWic_h); cudaGetSymbolAddress((void**)&BWic_l, g_BWic_l);
    cudaGetSymbolAddress((void**)&BUatt_h, g_BUatt_h); cudaGetSymbolAddress((void**)&BUatt_l, g_BUatt_l);
    cudaGetSymbolAddress((void**)&BWfb_h, g_BWfb_h); cudaGetSymbolAddress((void**)&BWfb_l, g_BWfb_l);
    cudaGetSymbolAddress((void**)&BWcat_h, g_BWcat_h); cudaGetSymbolAddress((void**)&BWcat_l, g_BWcat_l);
    cudaGetSymbolAddress((void**)&BWdo_h, g_BWdo_h); cudaGetSymbolAddress((void**)&BWdo_l, g_BWdo_l);
    cudaGetSymbolAddress((void**)&avgh, g_avgh);     cudaGetSymbolAddress((void**)&avgl, g_avgl);
    cudaGetSymbolAddress((void**)&Xh, g_Xh);         cudaGetSymbolAddress((void**)&Xl, g_Xl);
    cudaGetSymbolAddress((void**)&pWs, g_Ws);        cudaGetSymbolAddress((void**)&pavg, g_avg);
    cudaGetSymbolAddress((void**)&pc, g_c);          cudaGetSymbolAddress((void**)&pq, g_q);
    cudaGetSymbolAddress((void**)&pgate, g_gate);    cudaGetSymbolAddress((void**)&pgates, g_gates);
    cudaGetSymbolAddress((void**)&palpha, g_alpha);

    cudaFuncSetAttribute(tc_gemm<0>, cudaFuncAttributeMaxDynamicSharedMemorySize, SMEM_SZ);
    cudaFuncSetAttribute(tc_gemm<1>, cudaFuncAttributeMaxDynamicSharedMemorySize, SMEM_SZ);
    cudaFuncSetAttribute(tc_gemm<2>, cudaFuncAttributeMaxDynamicSharedMemorySize, SMEM_SZ);

    // one-time conversions
    {
        int n = BB * PP * EE;
        split_kernel<<<(n + 255) / 256, 256>>>(img, imgh, imgl, n);
        dim3 blk(32, 8);
        tsplit_kernel<<<dim3(16, 64), blk>>>(W_att, BWatt_h, BWatt_l, EE, HH, EE, 0);
        tsplit_kernel<<<dim3(16, 64), blk>>>(Wih,   BWih_h,  BWih_l,  EE, HH, EE, 0);
        tsplit_kernel<<<dim3(16, 64), blk>>>(Wic,   BWic_h,  BWic_l,  EE, HH, EE, 0);
        tsplit_kernel<<<dim3(16, 16), blk>>>(U_att, BUatt_h, BUatt_l, HH, HH, HH, 0);
        tsplit_kernel<<<dim3(64, 16), blk>>>(Wfb,   BWfb_h,  BWfb_l,  HH, EE, HH, 0);
        tsplit_kernel<<<dim3(64, 80), blk>>>(Wl,    BWcat_h, BWcat_l, 2560, G4, XK, 0);
        tsplit_kernel<<<dim3(64, 16), blk>>>(Ul,    BWcat_h, BWcat_l, HH,   G4, XK, 2560);
        tsplit_kernel<<<dim3(VPAD / 32, 16), blk>>>(Wdo, BWdo_h, BWdo_l, HH, VV, HH, 0);
    }

    // init: avg, h0 (-> g_q temp, split into X), c0
    avg_kernel<<<dim3(EE / 256, BB), 256>>>(img, pavg, avgh, avgl);
    tc_gemm<1><<<dim3(4, 1), 256, SMEM_SZ>>>(avgh, avgl, EE, BWih_h, BWih_l, bih, pq, HH, HH, EE);
    tc_gemm<1><<<dim3(4, 1), 256, SMEM_SZ>>>(avgh, avgl, EE, BWic_h, BWic_l, bic, pc, HH, HH, EE);
    splitH_kernel<<<(BB * HH) / 256, 256>>>(pq, Xh, Xl);

    // W_s = img @ W_att + bW  (25088 x 512)
    tc_gemm<0><<<dim3(4, 196), 256, SMEM_SZ>>>(imgh, imgl, EE, BWatt_h, BWatt_l, bW, pWs, HH, HH, EE);

    for (int t = 0; t < SS; t++) {
        tc_gemm<0><<<dim3(4, 1), 256, SMEM_SZ>>>(Xh + 2560, Xl + 2560, XK,
                                                 BUatt_h, BUatt_l, bU, pq, HH, HH, HH);
        attention_kernel<<<BB, 256>>>(pWs, pq, v_att, bv, palpha, alphas + (size_t)t * PP);
        tc_gemm<2><<<dim3(16, 1), 256, SMEM_SZ>>>(Xh + 2560, Xl + 2560, XK,
                                                  BWfb_h, BWfb_l, bfb, pgate, EE, EE, HH);
        context_kernel<<<dim3(EE / 256, BB), 256>>>(img, palpha, pgate, Xh, Xl);
        emb_kernel<<<(BB * HH) / 256, 256>>>(Wemb, cap, t, Xh, Xl);
        tc_gemm<0><<<dim3(16, 1), 256, SMEM_SZ>>>(Xh, Xl, XK,
                                                  BWcat_h, BWcat_l, bl, pgates, G4, G4, XK);
        lstm_kernel<<<(BB * HH) / 256, 256>>>(pgates, pc, Xh, Xl);
        tc_gemm<0><<<dim3(VPAD / 128, 1), 256, SMEM_SZ>>>(Xh + 2560, Xl + 2560, XK,
                                                          BWdo_h, BWdo_l, bdo,
                                                          preds + (size_t)t * VV,
                                                          SS * VV, VV, HH);
    }
}

// round 6
// speedup vs baseline: 2.2289x; 1.6948x over previous
#include <cuda_runtime.h>
#include <cuda_bf16.h>
#include <math.h>
#include <stdint.h>

#define BB 128
#define PP 196
#define EE 2048
#define HH 512
#define VV 10000
#define VPAD 10112
#define TT 20
#define SS 19
#define XK 3072
#define G4 2048

typedef __nv_bfloat16 bf16;

// ---------------- device global scratch ----------------
__device__ bf16  g_imgh[(size_t)BB * PP * EE];
__device__ bf16  g_imgl[(size_t)BB * PP * EE];
__device__ float g_Ws[(size_t)BB * PP * HH];
__device__ bf16  g_BWatt_h[HH * EE],  g_BWatt_l[HH * EE];
__device__ bf16  g_BWih_h[HH * EE],   g_BWih_l[HH * EE];
__device__ bf16  g_BWic_h[HH * EE],   g_BWic_l[HH * EE];
__device__ bf16  g_BUatt_h[HH * HH],  g_BUatt_l[HH * HH];
__device__ bf16  g_BWfb_h[EE * HH],   g_BWfb_l[EE * HH];
__device__ bf16  g_BWcat_h[(size_t)G4 * XK], g_BWcat_l[(size_t)G4 * XK];
__device__ bf16  g_BWdo_h[(size_t)VPAD * HH], g_BWdo_l[(size_t)VPAD * HH];
__device__ bf16  g_avgh[BB * EE], g_avgl[BB * EE];
__device__ bf16  g_Xh[BB * XK],   g_Xl[BB * XK];
__device__ float g_avg[BB * EE];
__device__ float g_c[BB * HH];
__device__ float g_alpha[BB * PP];
// split-K partial buffers (fp32). g_gatep doubles as h0 partials (8*BB*HH fits),
// g_gatesp doubles as c0 partials.
__device__ float g_qp[4 * BB * HH];
__device__ float g_gatep[4 * BB * EE];
__device__ float g_gatesp[3 * BB * G4];

// ---------------- helpers ----------------
__device__ __forceinline__ uint32_t s2u(const void* p) {
    uint32_t a;
    asm("{ .reg .u64 t; cvta.to.shared.u64 t, %1; cvt.u32.u64 %0, t; }" : "=r"(a) : "l"(p));
    return a;
}
__device__ __forceinline__ void cp16(uint32_t s, const void* g) {
    asm volatile("cp.async.cg.shared.global [%0], [%1], 16;" :: "r"(s), "l"(g) : "memory");
}
__device__ __forceinline__ void cp_commit() { asm volatile("cp.async.commit_group;" ::: "memory"); }
template <int N> __device__ __forceinline__ void cp_wait() {
    asm volatile("cp.async.wait_group %0;" :: "n"(N) : "memory");
}
__device__ __forceinline__ void ldsm4(uint32_t* r, uint32_t addr) {
    asm volatile("ldmatrix.sync.aligned.m8n8.x4.shared.b16 {%0,%1,%2,%3}, [%4];"
                 : "=r"(r[0]), "=r"(r[1]), "=r"(r[2]), "=r"(r[3]) : "r"(addr));
}
__device__ __forceinline__ void mma16816(float* d, const uint32_t* a, const uint32_t* b) {
    asm volatile("mma.sync.aligned.m16n8k16.row.col.f32.bf16.bf16.f32 "
                 "{%0,%1,%2,%3}, {%4,%5,%6,%7}, {%8,%9}, {%0,%1,%2,%3};"
                 : "+f"(d[0]), "+f"(d[1]), "+f"(d[2]), "+f"(d[3])
                 : "r"(a[0]), "r"(a[1]), "r"(a[2]), "r"(a[3]), "r"(b[0]), "r"(b[1]));
}
__device__ __forceinline__ float ex2f(float x) { float r; asm("ex2.approx.f32 %0,%1;" : "=f"(r) : "f"(x)); return r; }
__device__ __forceinline__ float rcpf(float x) { float r; asm("rcp.approx.f32 %0,%1;" : "=f"(r) : "f"(x)); return r; }
__device__ __forceinline__ float tanh_fast(float x) {
    float ax = fabsf(x);
    float e  = ex2f(ax * -2.8853900817779268f);
    float r  = (1.0f - e) * rcpf(1.0f + e);
    return copysignf(r, x);
}
__device__ __forceinline__ void split2(float v, bf16* ph, bf16* pl) {
    bf16 h = __float2bfloat16(v);
    *ph = h;
    *pl = __float2bfloat16(v - __bfloat162float(h));
}

// ---------------- split-bf16 HMMA GEMM, 4-stage pipeline, split-K via grid.z ----
// C[z][M,Nstore] = (A @ B^T) [+ bias if non-null], K-range z*(K/Z)..(z+1)*(K/Z)
// A: (Ah,Al)[M,K] bf16 stride lda.  B: (Bh,Bl)[Npad,K] bf16 stride K.
// CTA tile 128x128, BK=32, 8 warps (2M x 4N), warp tile 64x32.
#define TILE_B   10240          // 128 * 80
#define BUF_B    40960          // 4 tiles (Ah,Al,Bh,Bl)
#define SMEM_SZ  163840         // 4 stages

__global__ void __launch_bounds__(256, 1)
tc_gemm(const bf16* __restrict__ Ah, const bf16* __restrict__ Al, int lda,
        const bf16* __restrict__ Bh, const bf16* __restrict__ Bl,
        const float* __restrict__ bias, float* __restrict__ C, int ldc,
        int Nstore, int K)
{
    extern __shared__ char sm[];
    const int tid = threadIdx.x, lane = tid & 31, wid = tid >> 5;
    const int m0 = blockIdx.y << 7, n0 = blockIdx.x << 7;
    const int wy = wid & 1, wx = wid >> 1;
    const uint32_t sb = s2u(sm);

    const int kc = K / gridDim.z;            // this CTA's K extent
    const size_t kofs = (size_t)blockIdx.z * kc * 2;   // bytes
    C += (size_t)blockIdx.z * gridDim.y * 128 * ldc;

    const char* gAh = (const char*)(Ah + (size_t)m0 * lda) + kofs;
    const char* gAl = (const char*)(Al + (size_t)m0 * lda) + kofs;
    const char* gBh = (const char*)(Bh + (size_t)n0 * K) + kofs;
    const char* gBl = (const char*)(Bl + (size_t)n0 * K) + kofs;
    const size_t strA = (size_t)lda * 2, strB = (size_t)K * 2;

    const int arow = lane & 15;
    const int acol = (lane >> 4) << 4;
    const int brow = ((lane >> 4) << 3) + (lane & 7);
    const int bcol = ((lane >> 3) & 1) << 4;
    const uint32_t aoff = (uint32_t)((wy * 64 + arow) * 80 + acol);
    const uint32_t boff = (uint32_t)((wx * 32 + brow) * 80 + bcol);

    float acc[4][4][4] = {};
    const int nk = kc >> 5;

    auto issue = [&](int ch) {
        if (ch < nk) {
            const int k0b = ch << 6;
            const uint32_t s0 = sb + (ch & 3) * BUF_B;
            #pragma unroll
            for (int half = 0; half < 2; half++) {
                int u  = tid + half * 256;
                int r  = u >> 2;
                int sg = (u & 3) << 4;
                uint32_t s = s0 + r * 80 + sg;
                size_t gA = (size_t)r * strA + k0b + sg;
                size_t gB = (size_t)r * strB + k0b + sg;
                cp16(s,              gAh + gA);
                cp16(s + TILE_B,     gAl + gA);
                cp16(s + 2 * TILE_B, gBh + gB);
                cp16(s + 3 * TILE_B, gBl + gB);
            }
        }
        cp_commit();   // empty groups at tail keep wait_group counts valid
    };

    issue(0); issue(1); issue(2);

    for (int ch = 0; ch < nk; ch++) {
        cp_wait<2>();            // chunks ch+1, ch+2 may remain in flight
        __syncthreads();         // all reads of buffer (ch+3)&3 from iter ch-1 done
        issue(ch + 3);           // overlap next load with this chunk's compute

        const uint32_t base = sb + (ch & 3) * BUF_B;
        #pragma unroll
        for (int ks = 0; ks < 2; ks++) {
            uint32_t ah[4][4], al[4][4];
            #pragma unroll
            for (int mi = 0; mi < 4; mi++) {
                uint32_t o = aoff + mi * (16 * 80) + ks * 32;
                ldsm4(ah[mi], base + o);
                ldsm4(al[mi], base + TILE_B + o);
            }
            uint32_t bh[2][4], bl[2][4];
            #pragma unroll
            for (int nj = 0; nj < 2; nj++) {
                uint32_t o = boff + nj * (16 * 80) + ks * 32;
                ldsm4(bh[nj], base + 2 * TILE_B + o);
                ldsm4(bl[nj], base + 3 * TILE_B + o);
            }
            #pragma unroll
            for (int mi = 0; mi < 4; mi++) {
                #pragma unroll
                for (int n8 = 0; n8 < 4; n8++) {
                    const uint32_t* pbh = &bh[n8 >> 1][(n8 & 1) << 1];
                    const uint32_t* pbl = &bl[n8 >> 1][(n8 & 1) << 1];
                    mma16816(acc[mi][n8], ah[mi], pbh);
                    mma16816(acc[mi][n8], ah[mi], pbl);
                    mma16816(acc[mi][n8], al[mi], pbh);
                }
            }
        }
    }

    #pragma unroll
    for (int mi = 0; mi < 4; mi++) {
        #pragma unroll
        for (int n8 = 0; n8 < 4; n8++) {
            int mb = m0 + wy * 64 + mi * 16 + (lane >> 2);
            int nb = n0 + wx * 32 + n8 * 8 + ((lane & 3) << 1);
            #pragma unroll
            for (int g = 0; g < 2; g++) {
                int m = mb + g * 8;
                #pragma unroll
                for (int j = 0; j < 2; j++) {
                    int n = nb + j;
                    if (n < Nstore) {
                        float v = acc[mi][n8][g * 2 + j];
                        if (bias) v += bias[n];
                        C[(size_t)m * ldc + n] = v;
                    }
                }
            }
        }
    }
}

// ---------------- conversion kernels ----------------
__global__ void split_kernel(const float* __restrict__ src, bf16* __restrict__ dh,
                             bf16* __restrict__ dl, int n)
{
    int i = blockIdx.x * 256 + threadIdx.x;
    if (i < n) split2(src[i], dh + i, dl + i);
}

__global__ void tsplit_kernel(const float* __restrict__ src, bf16* __restrict__ dh,
                              bf16* __restrict__ dl, int Ksrc, int N, int dst_ld, int koff)
{
    __shared__ float t[32][33];
    const int n0 = blockIdx.x << 5, k0 = blockIdx.y << 5;
    #pragma unroll
    for (int j = 0; j < 4; j++) {
        int kk = k0 + threadIdx.y + (j << 3);
        int n  = n0 + threadIdx.x;
        t[threadIdx.y + (j << 3)][threadIdx.x] = (n < N) ? src[(size_t)kk * N + n] : 0.0f;
    }
    __syncthreads();
    #pragma unroll
    for (int j = 0; j < 4; j++) {
        int nn = n0 + threadIdx.y + (j << 3);
        int k  = k0 + threadIdx.x;
        size_t o = (size_t)nn * dst_ld + koff + k;
        split2(t[threadIdx.x][threadIdx.y + (j << 3)], dh + o, dl + o);
    }
}

// ---------------- pointwise / attention kernels ----------------
__global__ void avg_kernel(const float* __restrict__ img, float* __restrict__ avg,
                           bf16* __restrict__ ah, bf16* __restrict__ al)
{
    int b = blockIdx.y;
    int e = blockIdx.x * 256 + threadIdx.x;
    const float* ib = img + (size_t)b * PP * EE + e;
    float s = 0;
    #pragma unroll 4
    for (int p = 0; p < PP; p++) s += ib[(size_t)p * EE];
    float v = s * (1.0f / PP);
    avg[b * EE + e] = v;
    split2(v, ah + b * EE + e, al + b * EE + e);
}

// sum 8 partials each for h0/c0, tanh, write c and X h-slice
__global__ void combine_init(const float* __restrict__ hp, const float* __restrict__ cp,
                             const float* __restrict__ bih, const float* __restrict__ bic,
                             float* __restrict__ c, bf16* __restrict__ Xh, bf16* __restrict__ Xl)
{
    int i = blockIdx.x * 256 + threadIdx.x;   // B*H
    int b = i >> 9, h = i & 511;
    float sh = bih[h], sc = bic[h];
    #pragma unroll
    for (int z = 0; z < 8; z++) { sh += hp[z * BB * HH + i]; sc += cp[z * BB * HH + i]; }
    c[i] = tanhf(sc);
    size_t o = (size_t)b * XK + 2560 + h;
    split2(tanhf(sh), Xh + o, Xl + o);
}

__global__ void __launch_bounds__(256)
attention_kernel(const float* __restrict__ Ws, const float* __restrict__ qp,
                 const float* __restrict__ bU,
                 const float* __restrict__ v_att, const float* __restrict__ bv,
                 float* __restrict__ alpha, float* __restrict__ alpha_out)
{
    __shared__ float qs[HH], vs[HH], es[PP], red[8];
    const int b = blockIdx.x, tid = threadIdx.x;
    const int lane = tid & 31, warp = tid >> 5;

    for (int i = tid; i < HH; i += 256) {
        float s = bU[i];
        #pragma unroll
        for (int z = 0; z < 4; z++) s += qp[z * BB * HH + b * HH + i];
        qs[i] = s;
        vs[i] = v_att[i];
    }
    __syncthreads();

    const float* Wb = Ws + (size_t)b * PP * HH;
    const float bv0 = bv[0];
    for (int p = warp; p < PP; p += 8) {
        const float* row = Wb + (size_t)p * HH;
        float s = 0.0f;
        #pragma unroll
        for (int i = 0; i < HH / 32; i++) {
            int h = lane + 32 * i;
            s += vs[h] * tanh_fast(row[h] + qs[h]);
        }
        #pragma unroll
        for (int o = 16; o; o >>= 1) s += __shfl_xor_sync(0xffffffffu, s, o);
        if (lane == 0) es[p] = s + bv0;
    }
    __syncthreads();

    float m = -1e30f;
    for (int p = tid; p < PP; p += 256) m = fmaxf(m, es[p]);
    #pragma unroll
    for (int o = 16; o; o >>= 1) m = fmaxf(m, __shfl_xor_sync(0xffffffffu, m, o));
    if (lane == 0) red[warp] = m;
    __syncthreads();
    if (warp == 0) {
        float t = (lane < 8) ? red[lane] : -1e30f;
        #pragma unroll
        for (int o = 4; o; o >>= 1) t = fmaxf(t, __shfl_xor_sync(0xffffffffu, t, o));
        if (lane == 0) red[0] = t;
    }
    __syncthreads();
    m = red[0];
    __syncthreads();

    float sum = 0.0f;
    for (int p = tid; p < PP; p += 256) { float ev = expf(es[p] - m); es[p] = ev; sum += ev; }
    #pragma unroll
    for (int o = 16; o; o >>= 1) sum += __shfl_xor_sync(0xffffffffu, sum, o);
    if (lane == 0) red[warp] = sum;
    __syncthreads();
    if (warp == 0) {
        float t = (lane < 8) ? red[lane] : 0.0f;
        #pragma unroll
        for (int o = 4; o; o >>= 1) t += __shfl_xor_sync(0xffffffffu, t, o);
        if (lane == 0) red[0] = t;
    }
    __syncthreads();
    float inv = 1.0f / red[0];
    for (int p = tid; p < PP; p += 256) {
        float a = es[p] * inv;
        alpha[b * PP + p] = a;
        alpha_out[(size_t)b * (SS * PP) + p] = a;
    }
}

__global__ void context_kernel(const float* __restrict__ img, const float* __restrict__ alpha,
                               const float* __restrict__ gatep, const float* __restrict__ bfb,
                               bf16* __restrict__ Xh, bf16* __restrict__ Xl)
{
    __shared__ float al[PP];
    const int b = blockIdx.y;
    const int e = blockIdx.x * 256 + threadIdx.x;
    if (threadIdx.x < PP) al[threadIdx.x] = alpha[b * PP + threadIdx.x];
    __syncthreads();
    const float* ib = img + (size_t)b * PP * EE + e;
    float s0 = 0, s1 = 0, s2 = 0, s3 = 0;
    #pragma unroll 4
    for (int p = 0; p < PP; p += 4) {
        s0 += al[p    ] * ib[(size_t)(p    ) * EE];
        s1 += al[p + 1] * ib[(size_t)(p + 1) * EE];
        s2 += al[p + 2] * ib[(size_t)(p + 2) * EE];
        s3 += al[p + 3] * ib[(size_t)(p + 3) * EE];
    }
    float gs = bfb[e];
    #pragma unroll
    for (int z = 0; z < 4; z++) gs += gatep[(size_t)z * BB * EE + b * EE + e];
    float gate = 1.0f / (1.0f + expf(-gs));
    float v = (s0 + s1 + s2 + s3) * gate;
    size_t o = (size_t)b * XK + HH + e;
    split2(v, Xh + o, Xl + o);
}

__global__ void emb_kernel(const float* __restrict__ Wemb, const int* __restrict__ cap,
                           int t, bf16* __restrict__ Xh, bf16* __restrict__ Xl)
{
    int i = blockIdx.x * 256 + threadIdx.x;
    int b = i >> 9, h = i & 511;
    int c = cap[b * TT + t];
    size_t o = (size_t)b * XK + h;
    split2(Wemb[(size_t)c * HH + h], Xh + o, Xl + o);
}

__global__ void lstm_kernel(const float* __restrict__ gatesp, const float* __restrict__ bl,
                            float* __restrict__ c, bf16* __restrict__ Xh, bf16* __restrict__ Xl)
{
    int i = blockIdx.x * 256 + threadIdx.x;
    int b = i >> 9, h = i & 511;
    float g[4];
    #pragma unroll
    for (int k = 0; k < 4; k++) {
        int j = k * HH + h;
        float s = bl[j];
        #pragma unroll
        for (int z = 0; z < 3; z++) s += gatesp[(size_t)z * BB * G4 + b * G4 + j];
        g[k] = s;
    }
    float ig = 1.0f / (1.0f + expf(-g[0]));
    float fg = 1.0f / (1.0f + expf(-g[1]));
    float gg = tanhf(g[2]);
    float og = 1.0f / (1.0f + expf(-g[3]));
    float cn = fg * c[i] + ig * gg;
    c[i] = cn;
    size_t o = (size_t)b * XK + 2560 + h;
    split2(og * tanhf(cn), Xh + o, Xl + o);
}

// ---------------- host launch ----------------
extern "C" void kernel_launch(void* const* d_in, const int* in_sizes, int n_in,
                              void* d_out, int out_size)
{
    const float* img   = (const float*)d_in[0];
    const int*   cap   = (const int*)  d_in[1];
    const float* U_att = (const float*)d_in[2];
    const float* bU    = (const float*)d_in[3];
    const float* W_att = (const float*)d_in[4];
    const float* bW    = (const float*)d_in[5];
    const float* v_att = (const float*)d_in[6];
    const float* bv    = (const float*)d_in[7];
    const float* Wih   = (const float*)d_in[8];
    const float* bih   = (const float*)d_in[9];
    const float* Wic   = (const float*)d_in[10];
    const float* bic   = (const float*)d_in[11];
    const float* Wfb   = (const float*)d_in[12];
    const float* bfb   = (const float*)d_in[13];
    const float* Wdo   = (const float*)d_in[14];
    const float* bdo   = (const float*)d_in[15];
    const float* Wemb  = (const float*)d_in[16];
    const float* Wl    = (const float*)d_in[17];
    const float* Ul    = (const float*)d_in[18];
    const float* bl    = (const float*)d_in[19];

    float* preds  = (float*)d_out;
    float* alphas = (float*)d_out + (size_t)BB * SS * VV;

    bf16 *imgh, *imgl, *BWatt_h, *BWatt_l, *BWih_h, *BWih_l, *BWic_h, *BWic_l;
    bf16 *BUatt_h, *BUatt_l, *BWfb_h, *BWfb_l, *BWcat_h, *BWcat_l, *BWdo_h, *BWdo_l;
    bf16 *avgh, *avgl, *Xh, *Xl;
    float *pWs, *pavg, *pc, *palpha, *pqp, *pgatep, *pgatesp;
    cudaGetSymbolAddress((void**)&imgh, g_imgh);     cudaGetSymbolAddress((void**)&imgl, g_imgl);
    cudaGetSymbolAddress((void**)&BWatt_h, g_BWatt_h); cudaGetSymbolAddress((void**)&BWatt_l, g_BWatt_l);
    cudaGetSymbolAddress((void**)&BWih_h, g_BWih_h); cudaGetSymbolAddress((void**)&BWih_l, g_BWih_l);
    cudaGetSymbolAddress((void**)&BWic_h, g_BWic_h); cudaGetSymbolAddress((void**)&BWic_l, g_BWic_l);
    cudaGetSymbolAddress((void**)&BUatt_h, g_BUatt_h); cudaGetSymbolAddress((void**)&BUatt_l, g_BUatt_l);
    cudaGetSymbolAddress((void**)&BWfb_h, g_BWfb_h); cudaGetSymbolAddress((void**)&BWfb_l, g_BWfb_l);
    cudaGetSymbolAddress((void**)&BWcat_h, g_BWcat_h); cudaGetSymbolAddress((void**)&BWcat_l, g_BWcat_l);
    cudaGetSymbolAddress((void**)&BWdo_h, g_BWdo_h); cudaGetSymbolAddress((void**)&BWdo_l, g_BWdo_l);
    cudaGetSymbolAddress((void**)&avgh, g_avgh);     cudaGetSymbolAddress((void**)&avgl, g_avgl);
    cudaGetSymbolAddress((void**)&Xh, g_Xh);         cudaGetSymbolAddress((void**)&Xl, g_Xl);
    cudaGetSymbolAddress((void**)&pWs, g_Ws);        cudaGetSymbolAddress((void**)&pavg, g_avg);
    cudaGetSymbolAddress((void**)&pc, g_c);          cudaGetSymbolAddress((void**)&palpha, g_alpha);
    cudaGetSymbolAddress((void**)&pqp, g_qp);
    cudaGetSymbolAddress((void**)&pgatep, g_gatep);
    cudaGetSymbolAddress((void**)&pgatesp, g_gatesp);

    cudaFuncSetAttribute(tc_gemm, cudaFuncAttributeMaxDynamicSharedMemorySize, SMEM_SZ);

    // one-time conversions
    {
        int n = BB * PP * EE;
        split_kernel<<<(n + 255) / 256, 256>>>(img, imgh, imgl, n);
        dim3 blk(32, 8);
        tsplit_kernel<<<dim3(16, 64), blk>>>(W_att, BWatt_h, BWatt_l, EE, HH, EE, 0);
        tsplit_kernel<<<dim3(16, 64), blk>>>(Wih,   BWih_h,  BWih_l,  EE, HH, EE, 0);
        tsplit_kernel<<<dim3(16, 64), blk>>>(Wic,   BWic_h,  BWic_l,  EE, HH, EE, 0);
        tsplit_kernel<<<dim3(16, 16), blk>>>(U_att, BUatt_h, BUatt_l, HH, HH, HH, 0);
        tsplit_kernel<<<dim3(64, 16), blk>>>(Wfb,   BWfb_h,  BWfb_l,  HH, EE, HH, 0);
        tsplit_kernel<<<dim3(64, 80), blk>>>(Wl,    BWcat_h, BWcat_l, 2560, G4, XK, 0);
        tsplit_kernel<<<dim3(64, 16), blk>>>(Ul,    BWcat_h, BWcat_l, HH,   G4, XK, 2560);
        tsplit_kernel<<<dim3(VPAD / 32, 16), blk>>>(Wdo, BWdo_h, BWdo_l, HH, VV, HH, 0);
    }

    // init: avg -> h0/c0 partials (split-K x8) -> combine
    avg_kernel<<<dim3(EE / 256, BB), 256>>>(img, pavg, avgh, avgl);
    tc_gemm<<<dim3(4, 1, 8), 256, SMEM_SZ>>>(avgh, avgl, EE, BWih_h, BWih_l,
                                             nullptr, pgatep, HH, HH, EE);
    tc_gemm<<<dim3(4, 1, 8), 256, SMEM_SZ>>>(avgh, avgl, EE, BWic_h, BWic_l,
                                             nullptr, pgatesp, HH, HH, EE);
    combine_init<<<(BB * HH) / 256, 256>>>(pgatep, pgatesp, bih, bic, pc, Xh, Xl);

    // W_s = img @ W_att + bW
    tc_gemm<<<dim3(4, 196, 1), 256, SMEM_SZ>>>(imgh, imgl, EE, BWatt_h, BWatt_l,
                                               bW, pWs, HH, HH, EE);

    for (int t = 0; t < SS; t++) {
        // q partials (split-K x4), summed + bU in attention
        tc_gemm<<<dim3(4, 1, 4), 256, SMEM_SZ>>>(Xh + 2560, Xl + 2560, XK,
                                                 BUatt_h, BUatt_l, nullptr, pqp, HH, HH, HH);
        attention_kernel<<<BB, 256>>>(pWs, pqp, bU, v_att, bv, palpha, alphas + (size_t)t * PP);
        // gate partials (split-K x4), sigmoid in context
        tc_gemm<<<dim3(16, 1, 4), 256, SMEM_SZ>>>(Xh + 2560, Xl + 2560, XK,
                                                  BWfb_h, BWfb_l, nullptr, pgatep, EE, EE, HH);
        context_kernel<<<dim3(EE / 256, BB), 256>>>(img, palpha, pgatep, bfb, Xh, Xl);
        emb_kernel<<<(BB * HH) / 256, 256>>>(Wemb, cap, t, Xh, Xl);
        // gates partials (split-K x3), summed + bl in lstm
        tc_gemm<<<dim3(16, 1, 3), 256, SMEM_SZ>>>(Xh, Xl, XK,
                                                  BWcat_h, BWcat_l, nullptr, pgatesp, G4, G4, XK);
        lstm_kernel<<<(BB * HH) / 256, 256>>>(pgatesp, bl, pc, Xh, Xl);
        // preds (no split)
        tc_gemm<<<dim3(VPAD / 128, 1, 1), 256, SMEM_SZ>>>(Xh + 2560, Xl + 2560, XK,
                                                          BWdo_h, BWdo_l, bdo,
                                                          preds + (size_t)t * VV,
                                                          SS * VV, VV, HH);
    }
}